// round 1
// baseline (speedup 1.0000x reference)
#include <cuda_runtime.h>
#include <math.h>

#define TM  32        // batch rows per CTA
#define NT  256       // threads per CTA
#define PAD 36        // smem row stride in floats (16B-aligned, de-conflicted)

// ---- shared memory layout (in floats) ----
#define OFF_X1   0                        // [1024][PAD] X1 (later rows 0..511 hold X2 cols 512..1023)
#define OFF_X2   (1024*PAD)               // [512][PAD]  X2 cols 0..511 (later reused: H1 [256][PAD], H2 after)
#define OFF_X0   (OFF_X2 + 512*PAD)       // [32][PAD]
#define OFF_G1   (OFF_X0 + 32*PAD)        // 32 sigmoid gates layer1
#define OFF_G2   (OFF_G1 + 32)            // 32 sigmoid gates layer2
#define OFF_STAT (OFF_G2 + 32)            // 512 partial sums for LN
#define OFF_MU   (OFF_STAT + 512)         // 32
#define OFF_RS   (OFF_MU + 32)            // 32
#define OFF_W3   (OFF_RS + 32)            // 128 (Wq3)
#define SMEM_FLOATS (OFF_W3 + 128)        // = 57216 floats = 228864 bytes (< 227 KiB opt-in max)

__device__ __forceinline__ float acc_tanh(float x) {
    // accurate tanh even under --use_fast_math (avoids tanh.approx ~6e-4 abs err)
    float e = expf(2.0f * x);
    return 1.0f - 2.0f / (e + 1.0f);
}

__global__ __launch_bounds__(NT, 1)
void cor_critic_fused(const float* __restrict__ state, const float* __restrict__ action,
                      const float* __restrict__ W1, const float* __restrict__ b1, const float* __restrict__ g1,
                      const float* __restrict__ W2, const float* __restrict__ b2, const float* __restrict__ g2,
                      const float* __restrict__ Wq1, const float* __restrict__ bq1,
                      const float* __restrict__ ln1g, const float* __restrict__ ln1b,
                      const float* __restrict__ Wq2, const float* __restrict__ bq2,
                      const float* __restrict__ ln2g, const float* __restrict__ ln2b,
                      const float* __restrict__ Wq3, const float* __restrict__ bq3,
                      float* __restrict__ out)
{
    extern __shared__ float sm[];
    float* sX1 = sm + OFF_X1;
    float* sX2 = sm + OFF_X2;
    float* sX0 = sm + OFF_X0;

    const int tid  = threadIdx.x;
    const int row0 = blockIdx.x * TM;

    // ---- prologue: gates, Wq3, X0 staging ----
    if (tid < 32) {
        sm[OFF_G1 + tid] = 1.0f / (1.0f + expf(-__ldg(g1 + tid)));
        sm[OFF_G2 + tid] = 1.0f / (1.0f + expf(-__ldg(g2 + tid)));
    }
    if (tid < 128) sm[OFF_W3 + tid] = __ldg(Wq3 + tid);

    for (int i = tid; i < 32 * TM; i += NT) {
        int r = i >> 5, d = i & 31;
        float v = (d < 24) ? __ldg(state + (size_t)(row0 + r) * 24 + d)
                           : __ldg(action + (size_t)(row0 + r) * 8 + (d - 24));
        sX0[d * PAD + r] = v;
    }
    __syncthreads();

    // ---- Stage 1: X1 = tanh(X0 @ A1 + b1) * sig(g1)   (A1[d][n] = W1[n>>5][d][n&31]) ----
    #pragma unroll 1
    for (int p = 0; p < 2; ++p) {
        const int c0 = p * 512 + tid;
        const int c1 = c0 + 256;
        const float* pW0 = W1 + (c0 >> 5) * 1024 + (c0 & 31);  // stride 32 per d
        const float* pW1 = W1 + (c1 >> 5) * 1024 + (c1 & 31);
        float a0[TM], a1[TM];
        #pragma unroll
        for (int r = 0; r < TM; ++r) { a0[r] = 0.f; a1[r] = 0.f; }
        #pragma unroll 4
        for (int d = 0; d < 32; ++d) {
            float w0 = __ldg(pW0 + d * 32);
            float w1 = __ldg(pW1 + d * 32);
            const float4* xr = (const float4*)(sX0 + d * PAD);
            #pragma unroll
            for (int i = 0; i < 8; ++i) {
                float4 x = xr[i];
                a0[4*i+0] += x.x*w0; a0[4*i+1] += x.y*w0; a0[4*i+2] += x.z*w0; a0[4*i+3] += x.w*w0;
                a1[4*i+0] += x.x*w1; a1[4*i+1] += x.y*w1; a1[4*i+2] += x.z*w1; a1[4*i+3] += x.w*w1;
            }
        }
        float bb0 = __ldg(b1 + c0), gg0 = sm[OFF_G1 + (c0 >> 5)];
        float bb1 = __ldg(b1 + c1), gg1 = sm[OFF_G1 + (c1 >> 5)];
        float4* o0 = (float4*)(sX1 + c0 * PAD);
        float4* o1 = (float4*)(sX1 + c1 * PAD);
        #pragma unroll
        for (int i = 0; i < 8; ++i) {
            o0[i] = make_float4(acc_tanh(a0[4*i+0]+bb0)*gg0, acc_tanh(a0[4*i+1]+bb0)*gg0,
                                acc_tanh(a0[4*i+2]+bb0)*gg0, acc_tanh(a0[4*i+3]+bb0)*gg0);
            o1[i] = make_float4(acc_tanh(a1[4*i+0]+bb1)*gg1, acc_tanh(a1[4*i+1]+bb1)*gg1,
                                acc_tanh(a1[4*i+2]+bb1)*gg1, acc_tanh(a1[4*i+3]+bb1)*gg1);
        }
    }
    __syncthreads();

    // ---- Stage 2: X2 = tanh(X1 @ A2 + b2) * sig(g2)   (A2[d][n] = W2[n>>5][d][n&31]) ----
    // pass 0 -> sX2 rows 0..511 ; pass 1 -> sX1 rows 0..511 (X1 dead after its K-loop)
    #pragma unroll 1
    for (int p = 0; p < 2; ++p) {
        const int c0 = p * 512 + tid;
        const int c1 = c0 + 256;
        const float* pW0 = W2 + (size_t)(c0 >> 5) * 32768 + (c0 & 31);
        const float* pW1 = W2 + (size_t)(c1 >> 5) * 32768 + (c1 & 31);
        float a0[TM], a1[TM];
        #pragma unroll
        for (int r = 0; r < TM; ++r) { a0[r] = 0.f; a1[r] = 0.f; }

        float wa0[4], wa1[4];
        #pragma unroll
        for (int j = 0; j < 4; ++j) { wa0[j] = __ldg(pW0 + j*32); wa1[j] = __ldg(pW1 + j*32); }

        #pragma unroll 1
        for (int db = 0; db < 1024; db += 4) {
            const int dn = (db + 4 < 1024) ? (db + 4) : 0;   // 2+ iter L2-latency lookahead
            float wn0[4], wn1[4];
            #pragma unroll
            for (int j = 0; j < 4; ++j) { wn0[j] = __ldg(pW0 + (dn+j)*32); wn1[j] = __ldg(pW1 + (dn+j)*32); }
            #pragma unroll
            for (int j = 0; j < 4; ++j) {
                const float4* xr = (const float4*)(sX1 + (db + j) * PAD);
                float w0 = wa0[j], w1 = wa1[j];
                #pragma unroll
                for (int i = 0; i < 8; ++i) {
                    float4 x = xr[i];
                    a0[4*i+0] += x.x*w0; a0[4*i+1] += x.y*w0; a0[4*i+2] += x.z*w0; a0[4*i+3] += x.w*w0;
                    a1[4*i+0] += x.x*w1; a1[4*i+1] += x.y*w1; a1[4*i+2] += x.z*w1; a1[4*i+3] += x.w*w1;
                }
            }
            #pragma unroll
            for (int j = 0; j < 4; ++j) { wa0[j] = wn0[j]; wa1[j] = wn1[j]; }
        }

        float bb0 = __ldg(b2 + c0), gg0 = sm[OFF_G2 + (c0 >> 5)];
        float bb1 = __ldg(b2 + c1), gg1 = sm[OFF_G2 + (c1 >> 5)];
        if (p == 1) __syncthreads();   // everyone done reading sX1 before overwrite
        float4* o0 = (p == 0) ? (float4*)(sX2 + c0 * PAD) : (float4*)(sX1 + (c0 - 512) * PAD);
        float4* o1 = (p == 0) ? (float4*)(sX2 + c1 * PAD) : (float4*)(sX1 + (c1 - 512) * PAD);
        #pragma unroll
        for (int i = 0; i < 8; ++i) {
            o0[i] = make_float4(acc_tanh(a0[4*i+0]+bb0)*gg0, acc_tanh(a0[4*i+1]+bb0)*gg0,
                                acc_tanh(a0[4*i+2]+bb0)*gg0, acc_tanh(a0[4*i+3]+bb0)*gg0);
            o1[i] = make_float4(acc_tanh(a1[4*i+0]+bb1)*gg1, acc_tanh(a1[4*i+1]+bb1)*gg1,
                                acc_tanh(a1[4*i+2]+bb1)*gg1, acc_tanh(a1[4*i+3]+bb1)*gg1);
        }
    }
    __syncthreads();

    // ---- Stage 3: H1pre = X2 @ Wq1 ; thread owns column q = tid for all 32 rows ----
    float acc[TM];
    #pragma unroll
    for (int r = 0; r < TM; ++r) acc[r] = 0.f;
    #pragma unroll 1
    for (int s = 0; s < 2; ++s) {
        const float* xb    = (s == 0) ? sX2 : sX1;              // X2 halves
        const float* wbase = Wq1 + (size_t)(s * 512) * 256 + tid;
        float wc[4];
        #pragma unroll
        for (int j = 0; j < 4; ++j) wc[j] = __ldg(wbase + j * 256);
        #pragma unroll 1
        for (int nb = 0; nb < 512; nb += 4) {
            int nn = (nb + 4 < 512) ? (nb + 4) : 0;
            float wn[4];
            #pragma unroll
            for (int j = 0; j < 4; ++j) wn[j] = __ldg(wbase + (nn + j) * 256);
            #pragma unroll
            for (int j = 0; j < 4; ++j) {
                const float4* xr = (const float4*)(xb + (nb + j) * PAD);
                float w = wc[j];
                #pragma unroll
                for (int i = 0; i < 8; ++i) {
                    float4 x = xr[i];
                    acc[4*i+0] += x.x*w; acc[4*i+1] += x.y*w; acc[4*i+2] += x.z*w; acc[4*i+3] += x.w*w;
                }
            }
            #pragma unroll
            for (int j = 0; j < 4; ++j) wc[j] = wn[j];
        }
    }
    __syncthreads();               // all X2 reads done before H1 overwrites sX2 region
    {
        float bb = __ldg(bq1 + tid);
        float* h = sX2 + tid * PAD;    // sH1[q=tid][r]
        #pragma unroll
        for (int r = 0; r < TM; ++r) h[r] = acc[r] + bb;
    }
    __syncthreads();

    // ---- LN1 + relu (in place over sH1) ----
    {
        int r = tid & 31, seg = tid >> 5;
        float s = 0.f, s2 = 0.f;
        for (int q = seg * 32; q < seg * 32 + 32; ++q) {
            float v = sX2[q * PAD + r]; s += v; s2 += v * v;
        }
        sm[OFF_STAT + seg * 32 + r] = s;
        sm[OFF_STAT + 256 + seg * 32 + r] = s2;
    }
    __syncthreads();
    if (tid < 32) {
        float s = 0.f, s2 = 0.f;
        #pragma unroll
        for (int g = 0; g < 8; ++g) { s += sm[OFF_STAT + g*32 + tid]; s2 += sm[OFF_STAT + 256 + g*32 + tid]; }
        float mu = s * (1.0f / 256.0f);
        float var = s2 * (1.0f / 256.0f) - mu * mu;
        sm[OFF_MU + tid] = mu;
        sm[OFF_RS + tid] = rsqrtf(var + 1e-5f);
    }
    __syncthreads();
    {
        float gq = __ldg(ln1g + tid), bqv = __ldg(ln1b + tid);
        float* h = sX2 + tid * PAD;
        #pragma unroll
        for (int r = 0; r < TM; ++r) {
            float v = (h[r] - sm[OFF_MU + r]) * sm[OFF_RS + r] * gq + bqv;
            h[r] = fmaxf(v, 0.0f);
        }
    }
    __syncthreads();

    // ---- Stage 4: H2pre = H1 @ Wq2 (threads 0..127 own one column each) ----
    float* sH2 = sX2 + 256 * PAD;
    if (tid < 128) {
        float a[TM];
        #pragma unroll
        for (int r = 0; r < TM; ++r) a[r] = 0.f;
        const float* wbase = Wq2 + tid;
        #pragma unroll 4
        for (int n = 0; n < 256; ++n) {
            float w = __ldg(wbase + n * 128);
            const float4* xr = (const float4*)(sX2 + n * PAD);
            #pragma unroll
            for (int i = 0; i < 8; ++i) {
                float4 x = xr[i];
                a[4*i+0] += x.x*w; a[4*i+1] += x.y*w; a[4*i+2] += x.z*w; a[4*i+3] += x.w*w;
            }
        }
        float bb = __ldg(bq2 + tid);
        float* h = sH2 + tid * PAD;
        #pragma unroll
        for (int r = 0; r < TM; ++r) h[r] = a[r] + bb;
    }
    __syncthreads();

    // ---- LN2 + relu ----
    {
        int r = tid & 31, seg = tid >> 5;
        if (seg < 4) {
            float s = 0.f, s2 = 0.f;
            for (int q = seg * 32; q < seg * 32 + 32; ++q) {
                float v = sH2[q * PAD + r]; s += v; s2 += v * v;
            }
            sm[OFF_STAT + seg * 32 + r] = s;
            sm[OFF_STAT + 256 + seg * 32 + r] = s2;
        }
    }
    __syncthreads();
    if (tid < 32) {
        float s = 0.f, s2 = 0.f;
        #pragma unroll
        for (int g = 0; g < 4; ++g) { s += sm[OFF_STAT + g*32 + tid]; s2 += sm[OFF_STAT + 256 + g*32 + tid]; }
        float mu = s * (1.0f / 128.0f);
        float var = s2 * (1.0f / 128.0f) - mu * mu;
        sm[OFF_MU + tid] = mu;
        sm[OFF_RS + tid] = rsqrtf(var + 1e-5f);
    }
    __syncthreads();
    if (tid < 128) {
        float gq = __ldg(ln2g + tid), bqv = __ldg(ln2b + tid);
        float* h = sH2 + tid * PAD;
        #pragma unroll
        for (int r = 0; r < TM; ++r) {
            float v = (h[r] - sm[OFF_MU + r]) * sm[OFF_RS + r] * gq + bqv;
            h[r] = fmaxf(v, 0.0f);
        }
    }
    __syncthreads();

    // ---- Stage 5: out = H2 @ Wq3 + bq3 (one warp per 4 rows) ----
    {
        float bq3v = __ldg(bq3);
        int w = tid >> 5, lane = tid & 31;
        #pragma unroll
        for (int rr = 0; rr < 4; ++rr) {
            int r = w * 4 + rr;
            float s = 0.f;
            #pragma unroll
            for (int j = 0; j < 4; ++j) {
                int q = lane + j * 32;
                s += sH2[q * PAD + r] * sm[OFF_W3 + q];
            }
            #pragma unroll
            for (int off = 16; off; off >>= 1) s += __shfl_xor_sync(0xffffffffu, s, off);
            if (lane == 0) out[row0 + r] = s + bq3v;
        }
    }
}

extern "C" void kernel_launch(void* const* d_in, const int* in_sizes, int n_in,
                              void* d_out, int out_size) {
    const float* state  = (const float*)d_in[0];
    const float* action = (const float*)d_in[1];
    const float* W1  = (const float*)d_in[2];
    const float* b1  = (const float*)d_in[3];
    const float* g1  = (const float*)d_in[4];
    const float* W2  = (const float*)d_in[5];
    const float* b2  = (const float*)d_in[6];
    const float* g2  = (const float*)d_in[7];
    const float* Wq1 = (const float*)d_in[8];
    const float* bq1 = (const float*)d_in[9];
    const float* l1g = (const float*)d_in[10];
    const float* l1b = (const float*)d_in[11];
    const float* Wq2 = (const float*)d_in[12];
    const float* bq2 = (const float*)d_in[13];
    const float* l2g = (const float*)d_in[14];
    const float* l2b = (const float*)d_in[15];
    const float* Wq3 = (const float*)d_in[16];
    const float* bq3 = (const float*)d_in[17];
    float* out = (float*)d_out;

    int B = in_sizes[0] / 24;       // state is [B, 24]
    int grid = B / TM;
    size_t smem = (size_t)SMEM_FLOATS * sizeof(float);
    cudaFuncSetAttribute(cor_critic_fused, cudaFuncAttributeMaxDynamicSharedMemorySize, (int)smem);
    cor_critic_fused<<<grid, NT, smem>>>(state, action, W1, b1, g1, W2, b2, g2,
                                         Wq1, bq1, l1g, l1b, Wq2, bq2, l2g, l2b, Wq3, bq3, out);
}

// round 2
// speedup vs baseline: 1.0575x; 1.0575x over previous
#include <cuda_runtime.h>
#include <math.h>

typedef unsigned long long u64;

#define TM  32        // batch rows per CTA
#define NT  256       // threads per CTA
#define PAD 36        // smem row stride in floats (16B-aligned)

// ---- shared memory layout (floats) ----
#define OFF_X1   0                        // [1024][PAD]
#define OFF_X2   (1024*PAD)               // [512][PAD]
#define OFF_X0   (OFF_X2 + 512*PAD)       // [32][PAD]
#define OFF_G1   (OFF_X0 + 32*PAD)
#define OFF_G2   (OFF_G1 + 32)
#define OFF_STAT (OFF_G2 + 32)
#define OFF_MU   (OFF_STAT + 512)
#define OFF_RS   (OFF_MU + 32)
#define OFF_W3   (OFF_RS + 32)
#define SMEM_FLOATS (OFF_W3 + 128)        // 57216 floats = 228864 B

// ---- packed fp32x2 helpers (sm_103a FFMA2 via PTX) ----
__device__ __forceinline__ void fma2(u64 &acc, u64 x, u64 w) {
    asm("fma.rn.f32x2 %0, %1, %2, %0;" : "+l"(acc) : "l"(x), "l"(w));
}
__device__ __forceinline__ u64 pack2(float w) {
    u64 r; asm("mov.b64 %0, {%1, %1};" : "=l"(r) : "f"(w)); return r;
}
__device__ __forceinline__ float2 unpack2(u64 v) {
    float2 f; asm("mov.b64 {%0, %1}, %2;" : "=f"(f.x), "=f"(f.y) : "l"(v)); return f;
}
__device__ __forceinline__ float acc_tanh(float x) {
    float e = expf(2.0f * x);
    return 1.0f - 2.0f / (e + 1.0f);
}

__global__ __launch_bounds__(NT, 1)
void cor_critic_fused(const float* __restrict__ state, const float* __restrict__ action,
                      const float* __restrict__ W1, const float* __restrict__ b1, const float* __restrict__ g1,
                      const float* __restrict__ W2, const float* __restrict__ b2, const float* __restrict__ g2,
                      const float* __restrict__ Wq1, const float* __restrict__ bq1,
                      const float* __restrict__ ln1g, const float* __restrict__ ln1b,
                      const float* __restrict__ Wq2, const float* __restrict__ bq2,
                      const float* __restrict__ ln2g, const float* __restrict__ ln2b,
                      const float* __restrict__ Wq3, const float* __restrict__ bq3,
                      float* __restrict__ out)
{
    extern __shared__ float sm[];
    float* sX1 = sm + OFF_X1;
    float* sX2 = sm + OFF_X2;
    float* sX0 = sm + OFF_X0;

    const int tid  = threadIdx.x;
    const int row0 = blockIdx.x * TM;

    // ---- prologue ----
    if (tid < 32) {
        sm[OFF_G1 + tid] = 1.0f / (1.0f + expf(-__ldg(g1 + tid)));
        sm[OFF_G2 + tid] = 1.0f / (1.0f + expf(-__ldg(g2 + tid)));
    }
    if (tid < 128) sm[OFF_W3 + tid] = __ldg(Wq3 + tid);

    for (int i = tid; i < 32 * TM; i += NT) {
        int r = i >> 5, d = i & 31;
        float v = (d < 24) ? __ldg(state + (size_t)(row0 + r) * 24 + d)
                           : __ldg(action + (size_t)(row0 + r) * 8 + (d - 24));
        sX0[d * PAD + r] = v;
    }
    __syncthreads();

    // ---- Stage 1: X1 = tanh(X0 @ A1 + b1) * sig(g1) ----
    #pragma unroll 1
    for (int p = 0; p < 2; ++p) {
        const int c0 = p * 512 + tid, c1 = c0 + 256;
        const float* pW0 = W1 + (c0 >> 5) * 1024 + (c0 & 31);
        const float* pW1 = W1 + (c1 >> 5) * 1024 + (c1 & 31);
        u64 a0[16], a1[16];
        #pragma unroll
        for (int i = 0; i < 16; ++i) { a0[i] = 0ull; a1[i] = 0ull; }
        #pragma unroll 4
        for (int d = 0; d < 32; ++d) {
            u64 w20 = pack2(__ldg(pW0 + d * 32));
            u64 w21 = pack2(__ldg(pW1 + d * 32));
            const ulonglong2* xr = (const ulonglong2*)(sX0 + d * PAD);
            #pragma unroll
            for (int i = 0; i < 8; ++i) {
                ulonglong2 x = xr[i];
                fma2(a0[2*i], x.x, w20); fma2(a0[2*i+1], x.y, w20);
                fma2(a1[2*i], x.x, w21); fma2(a1[2*i+1], x.y, w21);
            }
        }
        float bb0 = __ldg(b1 + c0), gg0 = sm[OFF_G1 + (c0 >> 5)];
        float bb1 = __ldg(b1 + c1), gg1 = sm[OFF_G1 + (c1 >> 5)];
        float2* o0 = (float2*)(sX1 + c0 * PAD);
        float2* o1 = (float2*)(sX1 + c1 * PAD);
        #pragma unroll
        for (int i = 0; i < 16; ++i) {
            float2 v0 = unpack2(a0[i]), v1 = unpack2(a1[i]);
            o0[i] = make_float2(acc_tanh(v0.x+bb0)*gg0, acc_tanh(v0.y+bb0)*gg0);
            o1[i] = make_float2(acc_tanh(v1.x+bb1)*gg1, acc_tanh(v1.y+bb1)*gg1);
        }
    }
    __syncthreads();

    // ---- Stage 2: X2 = tanh(X1 @ A2 + b2) * sig(g2) ----
    #pragma unroll 1
    for (int p = 0; p < 2; ++p) {
        const int c0 = p * 512 + tid, c1 = c0 + 256;
        const float* pW0 = W2 + (size_t)(c0 >> 5) * 32768 + (c0 & 31);
        const float* pW1 = W2 + (size_t)(c1 >> 5) * 32768 + (c1 & 31);
        u64 a0[16], a1[16];
        #pragma unroll
        for (int i = 0; i < 16; ++i) { a0[i] = 0ull; a1[i] = 0ull; }

        float wa0[4], wa1[4];
        #pragma unroll
        for (int j = 0; j < 4; ++j) { wa0[j] = __ldg(pW0 + j*32); wa1[j] = __ldg(pW1 + j*32); }

        #pragma unroll 1
        for (int db = 0; db < 1024; db += 4) {
            const int dn = (db + 4 < 1024) ? (db + 4) : 0;
            float wn0[4], wn1[4];
            #pragma unroll
            for (int j = 0; j < 4; ++j) { wn0[j] = __ldg(pW0 + (dn+j)*32); wn1[j] = __ldg(pW1 + (dn+j)*32); }
            #pragma unroll
            for (int j = 0; j < 4; ++j) {
                const ulonglong2* xr = (const ulonglong2*)(sX1 + (db + j) * PAD);
                u64 w20 = pack2(wa0[j]), w21 = pack2(wa1[j]);
                #pragma unroll
                for (int i = 0; i < 8; ++i) {
                    ulonglong2 x = xr[i];
                    fma2(a0[2*i], x.x, w20); fma2(a0[2*i+1], x.y, w20);
                    fma2(a1[2*i], x.x, w21); fma2(a1[2*i+1], x.y, w21);
                }
            }
            #pragma unroll
            for (int j = 0; j < 4; ++j) { wa0[j] = wn0[j]; wa1[j] = wn1[j]; }
        }

        float bb0 = __ldg(b2 + c0), gg0 = sm[OFF_G2 + (c0 >> 5)];
        float bb1 = __ldg(b2 + c1), gg1 = sm[OFF_G2 + (c1 >> 5)];
        if (p == 1) __syncthreads();   // X1 reads done before overwrite
        float2* o0 = (p == 0) ? (float2*)(sX2 + c0 * PAD) : (float2*)(sX1 + (c0 - 512) * PAD);
        float2* o1 = (p == 0) ? (float2*)(sX2 + c1 * PAD) : (float2*)(sX1 + (c1 - 512) * PAD);
        #pragma unroll
        for (int i = 0; i < 16; ++i) {
            float2 v0 = unpack2(a0[i]), v1 = unpack2(a1[i]);
            o0[i] = make_float2(acc_tanh(v0.x+bb0)*gg0, acc_tanh(v0.y+bb0)*gg0);
            o1[i] = make_float2(acc_tanh(v1.x+bb1)*gg1, acc_tanh(v1.y+bb1)*gg1);
        }
    }
    __syncthreads();

    // ---- Stage 3: H1pre = X2 @ Wq1. Thread = 2 cols (cc, cc+128) x 16 rows (rh half) ----
    const int rh = tid >> 7;       // 0/1 row half
    const int cc = tid & 127;
    u64 A0[8], A1[8];
    #pragma unroll
    for (int i = 0; i < 8; ++i) { A0[i] = 0ull; A1[i] = 0ull; }
    #pragma unroll 1
    for (int s = 0; s < 2; ++s) {
        const float* xb = (s == 0) ? sX2 : sX1;
        const float* wb = Wq1 + (size_t)(s * 512) * 256;
        float wc0[4], wc1[4];
        #pragma unroll
        for (int j = 0; j < 4; ++j) { wc0[j] = __ldg(wb + j*256 + cc); wc1[j] = __ldg(wb + j*256 + cc + 128); }
        #pragma unroll 1
        for (int nb = 0; nb < 512; nb += 4) {
            int nn = (nb + 4 < 512) ? (nb + 4) : 0;
            float wn0[4], wn1[4];
            #pragma unroll
            for (int j = 0; j < 4; ++j) { wn0[j] = __ldg(wb + (nn+j)*256 + cc); wn1[j] = __ldg(wb + (nn+j)*256 + cc + 128); }
            #pragma unroll
            for (int j = 0; j < 4; ++j) {
                const ulonglong2* xr = (const ulonglong2*)(xb + (nb + j) * PAD + rh * 16);
                u64 w20 = pack2(wc0[j]), w21 = pack2(wc1[j]);
                #pragma unroll
                for (int i = 0; i < 4; ++i) {
                    ulonglong2 x = xr[i];
                    fma2(A0[2*i], x.x, w20); fma2(A0[2*i+1], x.y, w20);
                    fma2(A1[2*i], x.x, w21); fma2(A1[2*i+1], x.y, w21);
                }
            }
            #pragma unroll
            for (int j = 0; j < 4; ++j) { wc0[j] = wn0[j]; wc1[j] = wn1[j]; }
        }
    }
    __syncthreads();               // X2 reads done before H1 overwrites sX2
    {
        float bb0 = __ldg(bq1 + cc), bb1 = __ldg(bq1 + cc + 128);
        float* h0 = sX2 + cc * PAD + rh * 16;
        float* h1 = sX2 + (cc + 128) * PAD + rh * 16;
        #pragma unroll
        for (int i = 0; i < 8; ++i) {
            float2 v0 = unpack2(A0[i]), v1 = unpack2(A1[i]);
            h0[2*i] = v0.x + bb0; h0[2*i+1] = v0.y + bb0;
            h1[2*i] = v1.x + bb1; h1[2*i+1] = v1.y + bb1;
        }
    }
    __syncthreads();

    // ---- LN1 + relu over sH1 = sX2[256][PAD] ----
    {
        int r = tid & 31, seg = tid >> 5;
        float s = 0.f, s2 = 0.f;
        for (int q = seg * 32; q < seg * 32 + 32; ++q) {
            float v = sX2[q * PAD + r]; s += v; s2 += v * v;
        }
        sm[OFF_STAT + seg * 32 + r] = s;
        sm[OFF_STAT + 256 + seg * 32 + r] = s2;
    }
    __syncthreads();
    if (tid < 32) {
        float s = 0.f, s2 = 0.f;
        #pragma unroll
        for (int g = 0; g < 8; ++g) { s += sm[OFF_STAT + g*32 + tid]; s2 += sm[OFF_STAT + 256 + g*32 + tid]; }
        float mu = s * (1.0f / 256.0f);
        float var = s2 * (1.0f / 256.0f) - mu * mu;
        sm[OFF_MU + tid] = mu;
        sm[OFF_RS + tid] = rsqrtf(var + 1e-5f);
    }
    __syncthreads();
    {
        float gq = __ldg(ln1g + tid), bqv = __ldg(ln1b + tid);
        float* h = sX2 + tid * PAD;
        #pragma unroll
        for (int r = 0; r < TM; ++r) {
            float v = (h[r] - sm[OFF_MU + r]) * sm[OFF_RS + r] * gq + bqv;
            h[r] = fmaxf(v, 0.0f);
        }
    }
    __syncthreads();

    // ---- Stage 4: H2pre = H1 @ Wq2. Thread = 2 cols (c4, c4+64) x 8 rows (grp) ----
    float* sH2 = sX2 + 256 * PAD;
    {
        const int grp = tid >> 6;   // 0..3
        const int c4  = tid & 63;
        u64 B0[4], B1[4];
        #pragma unroll
        for (int i = 0; i < 4; ++i) { B0[i] = 0ull; B1[i] = 0ull; }
        const float* wb = Wq2 + c4;
        #pragma unroll 4
        for (int n = 0; n < 256; ++n) {
            u64 w20 = pack2(__ldg(wb + n * 128));
            u64 w21 = pack2(__ldg(wb + n * 128 + 64));
            const ulonglong2* xr = (const ulonglong2*)(sX2 + n * PAD + grp * 8);
            #pragma unroll
            for (int i = 0; i < 2; ++i) {
                ulonglong2 x = xr[i];
                fma2(B0[2*i], x.x, w20); fma2(B0[2*i+1], x.y, w20);
                fma2(B1[2*i], x.x, w21); fma2(B1[2*i+1], x.y, w21);
            }
        }
        float bb0 = __ldg(bq2 + c4), bb1 = __ldg(bq2 + c4 + 64);
        float* h0 = sH2 + c4 * PAD + grp * 8;
        float* h1 = sH2 + (c4 + 64) * PAD + grp * 8;
        #pragma unroll
        for (int i = 0; i < 4; ++i) {
            float2 v0 = unpack2(B0[i]), v1 = unpack2(B1[i]);
            h0[2*i] = v0.x + bb0; h0[2*i+1] = v0.y + bb0;
            h1[2*i] = v1.x + bb1; h1[2*i+1] = v1.y + bb1;
        }
    }
    __syncthreads();

    // ---- LN2 + relu ----
    {
        int r = tid & 31, seg = tid >> 5;
        if (seg < 4) {
            float s = 0.f, s2 = 0.f;
            for (int q = seg * 32; q < seg * 32 + 32; ++q) {
                float v = sH2[q * PAD + r]; s += v; s2 += v * v;
            }
            sm[OFF_STAT + seg * 32 + r] = s;
            sm[OFF_STAT + 256 + seg * 32 + r] = s2;
        }
    }
    __syncthreads();
    if (tid < 32) {
        float s = 0.f, s2 = 0.f;
        #pragma unroll
        for (int g = 0; g < 4; ++g) { s += sm[OFF_STAT + g*32 + tid]; s2 += sm[OFF_STAT + 256 + g*32 + tid]; }
        float mu = s * (1.0f / 128.0f);
        float var = s2 * (1.0f / 128.0f) - mu * mu;
        sm[OFF_MU + tid] = mu;
        sm[OFF_RS + tid] = rsqrtf(var + 1e-5f);
    }
    __syncthreads();
    if (tid < 128) {
        float gq = __ldg(ln2g + tid), bqv = __ldg(ln2b + tid);
        float* h = sH2 + tid * PAD;
        #pragma unroll
        for (int r = 0; r < TM; ++r) {
            float v = (h[r] - sm[OFF_MU + r]) * sm[OFF_RS + r] * gq + bqv;
            h[r] = fmaxf(v, 0.0f);
        }
    }
    __syncthreads();

    // ---- Stage 5: out = H2 @ Wq3 + bq3 ----
    {
        float bq3v = __ldg(bq3);
        int w = tid >> 5, lane = tid & 31;
        #pragma unroll
        for (int rr = 0; rr < 4; ++rr) {
            int r = w * 4 + rr;
            float s = 0.f;
            #pragma unroll
            for (int j = 0; j < 4; ++j) {
                int q = lane + j * 32;
                s += sH2[q * PAD + r] * sm[OFF_W3 + q];
            }
            #pragma unroll
            for (int off = 16; off; off >>= 1) s += __shfl_xor_sync(0xffffffffu, s, off);
            if (lane == 0) out[row0 + r] = s + bq3v;
        }
    }
}

extern "C" void kernel_launch(void* const* d_in, const int* in_sizes, int n_in,
                              void* d_out, int out_size) {
    const float* state  = (const float*)d_in[0];
    const float* action = (const float*)d_in[1];
    const float* W1  = (const float*)d_in[2];
    const float* b1  = (const float*)d_in[3];
    const float* g1  = (const float*)d_in[4];
    const float* W2  = (const float*)d_in[5];
    const float* b2  = (const float*)d_in[6];
    const float* g2  = (const float*)d_in[7];
    const float* Wq1 = (const float*)d_in[8];
    const float* bq1 = (const float*)d_in[9];
    const float* l1g = (const float*)d_in[10];
    const float* l1b = (const float*)d_in[11];
    const float* Wq2 = (const float*)d_in[12];
    const float* bq2 = (const float*)d_in[13];
    const float* l2g = (const float*)d_in[14];
    const float* l2b = (const float*)d_in[15];
    const float* Wq3 = (const float*)d_in[16];
    const float* bq3 = (const float*)d_in[17];
    float* out = (float*)d_out;

    int B = in_sizes[0] / 24;
    int grid = B / TM;
    size_t smem = (size_t)SMEM_FLOATS * sizeof(float);
    cudaFuncSetAttribute(cor_critic_fused, cudaFuncAttributeMaxDynamicSharedMemorySize, (int)smem);
    cor_critic_fused<<<grid, NT, smem>>>(state, action, W1, b1, g1, W2, b2, g2,
                                         Wq1, bq1, l1g, l1b, Wq2, bq2, l2g, l2b, Wq3, bq3, out);
}